// round 1
// baseline (speedup 1.0000x reference)
#include <cuda_runtime.h>
#include <cuda_bf16.h>

#define N_NODES 50000
#define MAX_E   800000
#define MAX_TOT (MAX_E + N_NODES)
#define F1 128
#define F2 64

// ---------------- scratch (no allocations allowed) ----------------
__device__ int   g_cnt[N_NODES];
__device__ int   g_cursor[N_NODES];
__device__ int   g_rowptr[N_NODES + 1];
__device__ int   g_col[MAX_TOT];
__device__ float g_nrm[MAX_TOT];
__device__ float g_dinv[N_NODES];
__device__ float g_H1[(size_t)N_NODES * F1];   // x @ W1
__device__ float g_A1[(size_t)N_NODES * F1];   // relu(agg + b1)
__device__ float g_H2[(size_t)N_NODES * F2];   // A1 @ W2
__device__ int   g_is64;

// ---------------- edge dtype probe ----------------
__global__ void k_detect(const void* ei) {
    const long long* p = (const long long*)ei;
    int ok = 1;
    for (int i = 0; i < 64; i++) {
        long long v = p[i];
        if (v < 0 || v >= N_NODES) { ok = 0; break; }
    }
    g_is64 = ok;
}

__device__ __forceinline__ int edge_at(const void* ei, int E, int which, int idx) {
    if (g_is64) return (int)((const long long*)ei)[(size_t)which * E + idx];
    return ((const int*)ei)[(size_t)which * E + idx];
}

// ---------------- degree / dinv ----------------
__global__ void k_init() {
    int i = blockIdx.x * blockDim.x + threadIdx.x;
    if (i < N_NODES) { g_cnt[i] = 1; g_cursor[i] = 0; }  // 1 = self loop
}

__global__ void k_degree(const void* __restrict__ ei, int E) {
    int e = blockIdx.x * blockDim.x + threadIdx.x;
    if (e < E) atomicAdd(&g_cnt[edge_at(ei, E, 1, e)], 1);
}

__global__ void k_dinv() {
    int i = blockIdx.x * blockDim.x + threadIdx.x;
    if (i < N_NODES) g_dinv[i] = rsqrtf((float)g_cnt[i]);   // cnt >= 1 always
}

// ---------------- exclusive scan (single block) ----------------
__global__ void k_scan() {
    const int T = 1024;
    int t = threadIdx.x;
    const int per = (N_NODES + T - 1) / T;
    int s = t * per;
    int e = min(s + per, N_NODES);
    int local = 0;
    for (int i = s; i < e; i++) local += g_cnt[i];
    __shared__ int sm[T];
    sm[t] = local;
    __syncthreads();
    for (int off = 1; off < T; off <<= 1) {
        int v = (t >= off) ? sm[t - off] : 0;
        __syncthreads();
        sm[t] += v;
        __syncthreads();
    }
    int run = sm[t] - local;   // exclusive prefix for this chunk
    for (int i = s; i < e; i++) { g_rowptr[i] = run; run += g_cnt[i]; }
    if (t == T - 1) g_rowptr[N_NODES] = sm[T - 1];
}

// ---------------- CSR scatter (edges + self loops) ----------------
__global__ void k_scatter(const void* __restrict__ ei, int E) {
    int i = blockIdx.x * blockDim.x + threadIdx.x;
    int tot = E + N_NODES;
    if (i >= tot) return;
    int s, d;
    if (i < E) { s = edge_at(ei, E, 0, i); d = edge_at(ei, E, 1, i); }
    else       { s = d = i - E; }
    int pos = g_rowptr[d] + atomicAdd(&g_cursor[d], 1);
    g_col[pos] = s;
    g_nrm[pos] = g_dinv[s] * g_dinv[d];
}

// ---------------- fp32 SGEMM: C[M,N] = A[M,K] @ B[K,N] ----------------
__global__ __launch_bounds__(256) void k_sgemm(int M, int N, int K,
        const float* __restrict__ A, const float* __restrict__ B,
        float* __restrict__ C) {
    const int BM = 64, BN = 64, BK = 16;
    __shared__ float As[BK][BM];
    __shared__ float Bs[BK][BN];
    int tid = threadIdx.x;
    int tx = tid & 15, ty = tid >> 4;
    int rowBase = blockIdx.y * BM, colBase = blockIdx.x * BN;
    int aRow = tid >> 2,  aCol = (tid & 3) << 2;
    int bRow = tid >> 4,  bCol = (tid & 15) << 2;
    float acc[4][4] = {};
    for (int k0 = 0; k0 < K; k0 += BK) {
        float4 av = make_float4(0.f, 0.f, 0.f, 0.f);
        int gr = rowBase + aRow;
        if (gr < M) av = *(const float4*)(A + (size_t)gr * K + k0 + aCol);
        As[aCol + 0][aRow] = av.x;
        As[aCol + 1][aRow] = av.y;
        As[aCol + 2][aRow] = av.z;
        As[aCol + 3][aRow] = av.w;
        *(float4*)&Bs[bRow][bCol] =
            *(const float4*)(B + (size_t)(k0 + bRow) * N + colBase + bCol);
        __syncthreads();
#pragma unroll
        for (int k = 0; k < BK; k++) {
            float a[4], b[4];
#pragma unroll
            for (int i = 0; i < 4; i++) a[i] = As[k][(ty << 2) + i];
#pragma unroll
            for (int j = 0; j < 4; j++) b[j] = Bs[k][(tx << 2) + j];
#pragma unroll
            for (int i = 0; i < 4; i++)
#pragma unroll
                for (int j = 0; j < 4; j++)
                    acc[i][j] = fmaf(a[i], b[j], acc[i][j]);
        }
        __syncthreads();
    }
#pragma unroll
    for (int i = 0; i < 4; i++) {
        int gr = rowBase + (ty << 2) + i;
        if (gr < M)
            *(float4*)(C + (size_t)gr * N + colBase + (tx << 2)) =
                make_float4(acc[i][0], acc[i][1], acc[i][2], acc[i][3]);
    }
}

// ---------------- layer-1 aggregation + bias + relu ----------------
__global__ __launch_bounds__(256) void k_agg1(const float* __restrict__ b1) {
    int warp = (blockIdx.x * blockDim.x + threadIdx.x) >> 5;
    if (warp >= N_NODES) return;
    int lane = threadIdx.x & 31;
    int beg = g_rowptr[warp], end = g_rowptr[warp + 1];
    float4 acc = make_float4(0.f, 0.f, 0.f, 0.f);
    int j = beg;
    for (; j + 2 <= end; j += 2) {
        int c0 = g_col[j], c1 = g_col[j + 1];
        float w0 = g_nrm[j], w1 = g_nrm[j + 1];
        float4 h0 = *(const float4*)(g_H1 + (size_t)c0 * F1 + (lane << 2));
        float4 h1 = *(const float4*)(g_H1 + (size_t)c1 * F1 + (lane << 2));
        acc.x = fmaf(h0.x, w0, fmaf(h1.x, w1, acc.x));
        acc.y = fmaf(h0.y, w0, fmaf(h1.y, w1, acc.y));
        acc.z = fmaf(h0.z, w0, fmaf(h1.z, w1, acc.z));
        acc.w = fmaf(h0.w, w0, fmaf(h1.w, w1, acc.w));
    }
    if (j < end) {
        int c0 = g_col[j];
        float w0 = g_nrm[j];
        float4 h0 = *(const float4*)(g_H1 + (size_t)c0 * F1 + (lane << 2));
        acc.x = fmaf(h0.x, w0, acc.x);
        acc.y = fmaf(h0.y, w0, acc.y);
        acc.z = fmaf(h0.z, w0, acc.z);
        acc.w = fmaf(h0.w, w0, acc.w);
    }
    float4 bb = *(const float4*)(b1 + (lane << 2));
    float4 o;
    o.x = fmaxf(acc.x + bb.x, 0.f);
    o.y = fmaxf(acc.y + bb.y, 0.f);
    o.z = fmaxf(acc.z + bb.z, 0.f);
    o.w = fmaxf(acc.w + bb.w, 0.f);
    *(float4*)(g_A1 + (size_t)warp * F1 + (lane << 2)) = o;
}

// ---------------- layer-2 aggregation + bias + softmax ----------------
__global__ __launch_bounds__(256) void k_agg2(const float* __restrict__ b2,
                                              float* __restrict__ out) {
    int warp = (blockIdx.x * blockDim.x + threadIdx.x) >> 5;
    if (warp >= N_NODES) return;
    int lane = threadIdx.x & 31;
    int beg = g_rowptr[warp], end = g_rowptr[warp + 1];
    float2 acc = make_float2(0.f, 0.f);
    int j = beg;
    for (; j + 2 <= end; j += 2) {
        int c0 = g_col[j], c1 = g_col[j + 1];
        float w0 = g_nrm[j], w1 = g_nrm[j + 1];
        float2 h0 = *(const float2*)(g_H2 + (size_t)c0 * F2 + (lane << 1));
        float2 h1 = *(const float2*)(g_H2 + (size_t)c1 * F2 + (lane << 1));
        acc.x = fmaf(h0.x, w0, fmaf(h1.x, w1, acc.x));
        acc.y = fmaf(h0.y, w0, fmaf(h1.y, w1, acc.y));
    }
    if (j < end) {
        int c0 = g_col[j];
        float w0 = g_nrm[j];
        float2 h0 = *(const float2*)(g_H2 + (size_t)c0 * F2 + (lane << 1));
        acc.x = fmaf(h0.x, w0, acc.x);
        acc.y = fmaf(h0.y, w0, acc.y);
    }
    float2 bb = *(const float2*)(b2 + (lane << 1));
    float l0 = acc.x + bb.x;
    float l1 = acc.y + bb.y;
    float m = fmaxf(l0, l1);
#pragma unroll
    for (int o = 16; o > 0; o >>= 1)
        m = fmaxf(m, __shfl_xor_sync(0xffffffffu, m, o));
    float e0 = __expf(l0 - m);
    float e1 = __expf(l1 - m);
    float s = e0 + e1;
#pragma unroll
    for (int o = 16; o > 0; o >>= 1)
        s += __shfl_xor_sync(0xffffffffu, s, o);
    float inv = 1.0f / s;
    *(float2*)(out + (size_t)warp * F2 + (lane << 1)) = make_float2(e0 * inv, e1 * inv);
}

// ---------------- launch ----------------
extern "C" void kernel_launch(void* const* d_in, const int* in_sizes, int n_in,
                              void* d_out, int out_size) {
    const float* x  = (const float*)d_in[0];
    const void*  ei = d_in[1];
    const float* W1 = (const float*)d_in[2];
    const float* b1 = (const float*)d_in[3];
    const float* W2 = (const float*)d_in[4];
    const float* b2 = (const float*)d_in[5];
    float* out = (float*)d_out;
    int E = in_sizes[1] / 2;

    float *H1, *A1, *H2;
    cudaGetSymbolAddress((void**)&H1, g_H1);
    cudaGetSymbolAddress((void**)&A1, g_A1);
    cudaGetSymbolAddress((void**)&H2, g_H2);

    int mTiles = (N_NODES + 63) / 64;

    k_detect<<<1, 1>>>(ei);
    k_init<<<(N_NODES + 255) / 256, 256>>>();
    k_degree<<<(E + 255) / 256, 256>>>(ei, E);
    k_dinv<<<(N_NODES + 255) / 256, 256>>>();
    k_scan<<<1, 1024>>>();
    k_scatter<<<(E + N_NODES + 255) / 256, 256>>>(ei, E);

    k_sgemm<<<dim3(F1 / 64, mTiles), 256>>>(N_NODES, F1, F1, x, W1, H1);
    k_agg1<<<(N_NODES * 32 + 255) / 256, 256>>>(b1);
    k_sgemm<<<dim3(F2 / 64, mTiles), 256>>>(N_NODES, F2, F1, A1, W2, H2);
    k_agg2<<<(N_NODES * 32 + 255) / 256, 256>>>(b2, out);
}